// round 1
// baseline (speedup 1.0000x reference)
#include <cuda_runtime.h>
#include <math.h>

#define BSZ 16
#define NN 768
#define INDIM 16
#define HID 64
#define EMB 128
#define NH 8
#define BN (BSZ*NN)        // 12288
#define FDIM (NH*HID)      // 512
#define BHN (BSZ*NH*NN)    // 98304

// ---- static scratch (no cudaMalloc allowed) ----
__device__ float g_h0 [BN*HID];
__device__ float g_Wh [BN*FDIM];
__device__ float g_hc1[BN*FDIM];
__device__ float g_hc2[BN*FDIM];
__device__ float g_s1[BHN], g_s2[BHN], g_E2[BHN], g_F2[BHN];
__device__ float g_s2max[BSZ*NH];
__device__ float g_B0[HID*FDIM];
__device__ float g_B1[FDIM*FDIM];

// Rearrange gat_w[h][f][o] -> B[f][h*64+o] so Wh is one row-major GEMM.
__global__ void prep_B(const float* __restrict__ w0, const float* __restrict__ w1) {
    int i = blockIdx.x * blockDim.x + threadIdx.x;
    if (i < HID*FDIM) {
        int f = i / FDIM, c = i % FDIM, h = c / HID, o = c % HID;
        g_B0[i] = w0[(h*HID + f)*HID + o];
    }
    for (int j = i; j < FDIM*FDIM; j += gridDim.x * blockDim.x) {
        int f = j / FDIM, c = j % FDIM, h = c / HID, o = c % HID;
        g_B1[j] = w1[(h*FDIM + f)*HID + o];
    }
}

// Tiled SGEMM: C[M,N] = A[M,K] @ B[K,N] (+bias). BM=BN=64, BK=16, 256 thr, 4x4/thr.
// Requires M%64==0, N%64==0, K%16==0 (true for all call sites).
__global__ void sgemm(const float* __restrict__ A, const float* __restrict__ B,
                      const float* __restrict__ bias, float* __restrict__ C,
                      int M, int N, int K) {
    __shared__ float As[16][64];
    __shared__ float Bs[16][64];
    int tid = threadIdx.x;
    int m0 = blockIdx.x * 64, n0 = blockIdx.y * 64;
    int tx = tid & 15, ty = tid >> 4;
    int arow = tid >> 2, acol = (tid & 3) * 4;
    int brow = tid >> 4, bcol = (tid & 15) * 4;
    float acc[4][4] = {};
    for (int kc = 0; kc < K; kc += 16) {
        float4 av = *(const float4*)&A[(size_t)(m0 + arow) * K + kc + acol];
        As[acol+0][arow] = av.x; As[acol+1][arow] = av.y;
        As[acol+2][arow] = av.z; As[acol+3][arow] = av.w;
        *(float4*)&Bs[brow][bcol] = *(const float4*)&B[(size_t)(kc + brow) * N + n0 + bcol];
        __syncthreads();
#pragma unroll
        for (int k = 0; k < 16; k++) {
            float4 a4 = *(float4*)&As[k][ty*4];
            float4 b4 = *(float4*)&Bs[k][tx*4];
            float a[4] = {a4.x, a4.y, a4.z, a4.w};
            float b[4] = {b4.x, b4.y, b4.z, b4.w};
#pragma unroll
            for (int i = 0; i < 4; i++)
#pragma unroll
                for (int j = 0; j < 4; j++) acc[i][j] += a[i] * b[j];
        }
        __syncthreads();
    }
#pragma unroll
    for (int i = 0; i < 4; i++) {
        int m = m0 + ty*4 + i, n = n0 + tx*4;
        float4 v = {acc[i][0], acc[i][1], acc[i][2], acc[i][3]};
        if (bias) { v.x += bias[n]; v.y += bias[n+1]; v.z += bias[n+2]; v.w += bias[n+3]; }
        *(float4*)&C[(size_t)m * N + n] = v;
    }
}

// s1[bh,n] = Wh_row . a1[h],  s2 = Wh_row . a2[h]. One warp per (b,h,n).
__global__ void score_kernel(const float* __restrict__ Wh, const float* __restrict__ a,
                             float* __restrict__ s1, float* __restrict__ s2) {
    int warp = (blockIdx.x * blockDim.x + threadIdx.x) >> 5;
    int lane = threadIdx.x & 31;
    if (warp >= BHN) return;
    int n = warp % NN, bh = warp / NN, h = bh % NH, b = bh / NH;
    const float* wr = Wh + (size_t)(b*NN + n) * FDIM + h * HID;
    const float* ah = a + h * 2 * HID;
    float v0 = wr[lane], v1 = wr[lane + 32];
    float p1 = v0 * ah[lane]       + v1 * ah[lane + 32];
    float p2 = v0 * ah[HID + lane] + v1 * ah[HID + lane + 32];
#pragma unroll
    for (int off = 16; off; off >>= 1) {
        p1 += __shfl_xor_sync(0xffffffffu, p1, off);
        p2 += __shfl_xor_sync(0xffffffffu, p2, off);
    }
    if (lane == 0) { s1[warp] = p1; s2[warp] = p2; }
}

// Per (b,h): s2max, then E2 = exp(s2-s2max), F2 = exp(0.2*(s2-s2max)).
__global__ void prep_attn(const float* __restrict__ s2, float* __restrict__ E2,
                          float* __restrict__ F2, float* __restrict__ s2max) {
    int bh = blockIdx.x, tid = threadIdx.x;
    __shared__ float red[256];
    float mx = -1e30f;
    for (int i = tid; i < NN; i += 256) mx = fmaxf(mx, s2[bh*NN + i]);
    red[tid] = mx; __syncthreads();
    for (int s = 128; s; s >>= 1) {
        if (tid < s) red[tid] = fmaxf(red[tid], red[tid + s]);
        __syncthreads();
    }
    float m = red[0];
    if (tid == 0) s2max[bh] = m;
    for (int i = tid; i < NN; i += 256) {
        float d = s2[bh*NN + i] - m;
        E2[bh*NN + i] = expf(d);
        F2[bh*NN + i] = expf(0.2f * d);
    }
}

// Attention: out[b,n,h*64+o] = sum_m w(n,m) Wh[b,m,h*64+o] / sum_m w(n,m)
// w(n,m) = (s2[m] > -s1[n]) ? E1[n]*E2[m] : F1[n]*F2[m]   (exact exp(leaky - rowmax))
// Block: 128 n-rows x 64 o, 256 threads = 8 oT (8 o each) x 32 nT (4 rows each).
__global__ void attn_kernel(const float* __restrict__ Wh, const float* __restrict__ s1,
                            const float* __restrict__ s2, const float* __restrict__ E2,
                            const float* __restrict__ F2, const float* __restrict__ s2max,
                            float* __restrict__ out) {
    __shared__ float Whs[32 * 64];
    __shared__ float s2s[32], E2s[32], F2s[32];
    int bh = blockIdx.y, h = bh % NH, b = bh / NH;
    int n0 = blockIdx.x * 128;
    int tid = threadIdx.x;
    int oT = tid & 7, nT = tid >> 3;
    float smax = s2max[bh];
    float e1[4], f1[4], thr[4], wsum[4] = {};
    float acc[4][8] = {};
    int rows[4];
#pragma unroll
    for (int q = 0; q < 4; q++) {
        int r = n0 + q*32 + nT; rows[q] = r;
        float s1v = s1[bh*NN + r];
        float u = s1v + smax;
        float rmax = u > 0.f ? u : 0.2f * u;      // leaky(s1 + s2max) = exact row max
        e1[q] = expf(u - rmax);
        f1[q] = expf(0.2f * u - rmax);
        thr[q] = -s1v;
    }
    const float* whbase = Wh + (size_t)b * NN * FDIM + h * HID;
    for (int mt = 0; mt < NN; mt += 32) {
        __syncthreads();
#pragma unroll
        for (int l = 0; l < 2; l++) {
            int fi = tid + l * 256;                 // 512 float4 = 2048 floats
            int mm = fi >> 4;
            int o4 = (fi & 15) * 4;
            *(float4*)&Whs[mm*64 + o4] =
                *(const float4*)&whbase[(size_t)(mt + mm) * FDIM + o4];
        }
        if (tid < 32) {
            s2s[tid] = s2[bh*NN + mt + tid];
            E2s[tid] = E2[bh*NN + mt + tid];
            F2s[tid] = F2[bh*NN + mt + tid];
        }
        __syncthreads();
#pragma unroll 4
        for (int mm = 0; mm < 32; mm++) {
            float4 w0 = *(float4*)&Whs[mm*64 + oT*8];
            float4 w1 = *(float4*)&Whs[mm*64 + oT*8 + 4];
            float s2m = s2s[mm], E2m = E2s[mm], F2m = F2s[mm];
#pragma unroll
            for (int q = 0; q < 4; q++) {
                bool pos = s2m > thr[q];
                float w = (pos ? e1[q] : f1[q]) * (pos ? E2m : F2m);
                wsum[q] += w;
                acc[q][0] += w * w0.x; acc[q][1] += w * w0.y;
                acc[q][2] += w * w0.z; acc[q][3] += w * w0.w;
                acc[q][4] += w * w1.x; acc[q][5] += w * w1.y;
                acc[q][6] += w * w1.z; acc[q][7] += w * w1.w;
            }
        }
    }
#pragma unroll
    for (int q = 0; q < 4; q++) {
        float inv = 1.f / wsum[q];
        float* op = out + (size_t)(b*NN + rows[q]) * FDIM + h * HID + oT * 8;
        float4 v0 = {acc[q][0]*inv, acc[q][1]*inv, acc[q][2]*inv, acc[q][3]*inv};
        float4 v1 = {acc[q][4]*inv, acc[q][5]*inv, acc[q][6]*inv, acc[q][7]*inv};
        *(float4*)op = v0;
        *(float4*)&op[4] = v1;
    }
}

extern "C" void kernel_launch(void* const* d_in, const int* in_sizes, int n_in,
                              void* d_out, int out_size) {
    const float* x    = (const float*)d_in[0];
    const float* ip_w = (const float*)d_in[1];
    const float* ip_b = (const float*)d_in[2];
    const float* w0   = (const float*)d_in[3];
    const float* a0   = (const float*)d_in[4];
    const float* w1   = (const float*)d_in[5];
    const float* a1   = (const float*)d_in[6];
    const float* pw   = (const float*)d_in[7];
    const float* pb   = (const float*)d_in[8];
    float* out = (float*)d_out;

    float *h0, *Wh, *hc1, *hc2, *s1, *s2, *E2, *F2, *smax, *B0, *B1;
    cudaGetSymbolAddress((void**)&h0,   g_h0);
    cudaGetSymbolAddress((void**)&Wh,   g_Wh);
    cudaGetSymbolAddress((void**)&hc1,  g_hc1);
    cudaGetSymbolAddress((void**)&hc2,  g_hc2);
    cudaGetSymbolAddress((void**)&s1,   g_s1);
    cudaGetSymbolAddress((void**)&s2,   g_s2);
    cudaGetSymbolAddress((void**)&E2,   g_E2);
    cudaGetSymbolAddress((void**)&F2,   g_F2);
    cudaGetSymbolAddress((void**)&smax, g_s2max);
    cudaGetSymbolAddress((void**)&B0,   g_B0);
    cudaGetSymbolAddress((void**)&B1,   g_B1);

    prep_B<<<512, 256>>>(w0, w1);

    // input projection: h0 = x @ ip_w + ip_b   [12288,16]x[16,64]
    sgemm<<<dim3(BN/64, HID/64), 256>>>(x, ip_w, ip_b, h0, BN, HID, INDIM);

    // ---- GAT layer 0 ----
    sgemm<<<dim3(BN/64, FDIM/64), 256>>>(h0, B0, nullptr, Wh, BN, FDIM, HID);
    score_kernel<<<BHN/8, 256>>>(Wh, a0, s1, s2);
    prep_attn<<<BSZ*NH, 256>>>(s2, E2, F2, smax);
    attn_kernel<<<dim3(NN/128, BSZ*NH), 256>>>(Wh, s1, s2, E2, F2, smax, hc1);

    // ---- GAT layer 1 ----
    sgemm<<<dim3(BN/64, FDIM/64), 256>>>(hc1, B1, nullptr, Wh, BN, FDIM, FDIM);
    score_kernel<<<BHN/8, 256>>>(Wh, a1, s1, s2);
    prep_attn<<<BSZ*NH, 256>>>(s2, E2, F2, smax);
    attn_kernel<<<dim3(NN/128, BSZ*NH), 256>>>(Wh, s1, s2, E2, F2, smax, hc2);

    // output projection: out = hc2 @ proj_w + proj_b   [12288,512]x[512,128]
    sgemm<<<dim3(BN/64, EMB/64), 256>>>(hc2, pw, pb, out, BN, EMB, FDIM);
}

// round 2
// speedup vs baseline: 1.7901x; 1.7901x over previous
#include <cuda_runtime.h>
#include <math.h>

#define BSZ 16
#define NN 768
#define INDIM 16
#define HID 64
#define EMB 128
#define NH 8
#define BN (BSZ*NN)        // 12288
#define FDIM (NH*HID)      // 512
#define BH (BSZ*NH)        // 128
#define BHN (BH*NN)        // 98304
#define CH 96
#define NCH 8              // CH*NCH = 768

// ---- static scratch (no cudaMalloc allowed) ----
__device__ float g_h0 [BN*HID];
__device__ float g_Wh [BN*FDIM];
__device__ float g_hc1[BN*FDIM];
__device__ float g_hc2[BN*FDIM];
__device__ float g_s1[BHN], g_s2[BHN];
__device__ float g_s2s[BHN], g_E2s[BHN], g_F2s[BHN];   // sorted-order arrays
__device__ int   g_perm[BHN];
__device__ float g_s2max[BH];
__device__ float g_preF2[BH*(NN+1)], g_sufE2[BH*(NN+1)];
__device__ float g_PreF[(size_t)BH*(NN+1)*HID];        // 25.2 MB
__device__ float g_SufE[(size_t)BH*(NN+1)*HID];        // 25.2 MB
__device__ float g_chunkF[BH*NCH*HID], g_chunkE[BH*NCH*HID];
__device__ float g_B0[HID*FDIM];
__device__ float g_B1[FDIM*FDIM];

// Rearrange gat_w[h][f][o] -> B[f][h*64+o] so Wh is one row-major GEMM.
__global__ void prep_B(const float* __restrict__ w0, const float* __restrict__ w1) {
    int i = blockIdx.x * blockDim.x + threadIdx.x;
    if (i < HID*FDIM) {
        int f = i / FDIM, c = i % FDIM, h = c / HID, o = c % HID;
        g_B0[i] = w0[(h*HID + f)*HID + o];
    }
    for (int j = i; j < FDIM*FDIM; j += gridDim.x * blockDim.x) {
        int f = j / FDIM, c = j % FDIM, h = c / HID, o = c % HID;
        g_B1[j] = w1[(h*FDIM + f)*HID + o];
    }
}

// Tiled SGEMM: C[M,N] = A[M,K] @ B[K,N] (+bias). BM=BN=64, BK=16, 256 thr, 4x4/thr.
__global__ void sgemm(const float* __restrict__ A, const float* __restrict__ B,
                      const float* __restrict__ bias, float* __restrict__ C,
                      int M, int N, int K) {
    __shared__ float As[16][64];
    __shared__ float Bs[16][64];
    int tid = threadIdx.x;
    int m0 = blockIdx.x * 64, n0 = blockIdx.y * 64;
    int tx = tid & 15, ty = tid >> 4;
    int arow = tid >> 2, acol = (tid & 3) * 4;
    int brow = tid >> 4, bcol = (tid & 15) * 4;
    float acc[4][4] = {};
    for (int kc = 0; kc < K; kc += 16) {
        float4 av = *(const float4*)&A[(size_t)(m0 + arow) * K + kc + acol];
        As[acol+0][arow] = av.x; As[acol+1][arow] = av.y;
        As[acol+2][arow] = av.z; As[acol+3][arow] = av.w;
        *(float4*)&Bs[brow][bcol] = *(const float4*)&B[(size_t)(kc + brow) * N + n0 + bcol];
        __syncthreads();
#pragma unroll
        for (int k = 0; k < 16; k++) {
            float4 a4 = *(float4*)&As[k][ty*4];
            float4 b4 = *(float4*)&Bs[k][tx*4];
            float a[4] = {a4.x, a4.y, a4.z, a4.w};
            float b[4] = {b4.x, b4.y, b4.z, b4.w};
#pragma unroll
            for (int i = 0; i < 4; i++)
#pragma unroll
                for (int j = 0; j < 4; j++) acc[i][j] += a[i] * b[j];
        }
        __syncthreads();
    }
#pragma unroll
    for (int i = 0; i < 4; i++) {
        int m = m0 + ty*4 + i, n = n0 + tx*4;
        float4 v = {acc[i][0], acc[i][1], acc[i][2], acc[i][3]};
        if (bias) { v.x += bias[n]; v.y += bias[n+1]; v.z += bias[n+2]; v.w += bias[n+3]; }
        *(float4*)&C[(size_t)m * N + n] = v;
    }
}

// s1[bh,n] = Wh_row . a1[h],  s2 = Wh_row . a2[h]. One warp per (b,h,n).
__global__ void score_kernel(const float* __restrict__ Wh, const float* __restrict__ a,
                             float* __restrict__ s1, float* __restrict__ s2) {
    int warp = (blockIdx.x * blockDim.x + threadIdx.x) >> 5;
    int lane = threadIdx.x & 31;
    if (warp >= BHN) return;
    int n = warp % NN, bh = warp / NN, h = bh % NH, b = bh / NH;
    const float* wr = Wh + (size_t)(b*NN + n) * FDIM + h * HID;
    const float* ah = a + h * 2 * HID;
    float v0 = wr[lane], v1 = wr[lane + 32];
    float p1 = v0 * ah[lane]       + v1 * ah[lane + 32];
    float p2 = v0 * ah[HID + lane] + v1 * ah[HID + lane + 32];
#pragma unroll
    for (int off = 16; off; off >>= 1) {
        p1 += __shfl_xor_sync(0xffffffffu, p1, off);
        p2 += __shfl_xor_sync(0xffffffffu, p2, off);
    }
    if (lane == 0) { s1[warp] = p1; s2[warp] = p2; }
}

// Per (b,h): bitonic-sort s2 (with permutation), compute E2/F2 in sorted order,
// and serial scalar prefix/suffix sums of F2/E2. One block of 256 per bh.
__global__ void sort_prep(const float* __restrict__ s2) {
    __shared__ float sv[1024];
    __shared__ int   si[1024];
    __shared__ float fe[NN], ff[NN];
    int bh = blockIdx.x, tid = threadIdx.x;
    for (int i = tid; i < 1024; i += 256) {
        sv[i] = (i < NN) ? s2[bh*NN + i] : 3.0e38f;
        si[i] = i;
    }
    __syncthreads();
    for (int k = 2; k <= 1024; k <<= 1) {
        for (int j = k >> 1; j > 0; j >>= 1) {
            for (int i = tid; i < 1024; i += 256) {
                int ixj = i ^ j;
                if (ixj > i) {
                    bool up = ((i & k) == 0);
                    float a = sv[i], b = sv[ixj];
                    if ((a > b) == up) {
                        sv[i] = b; sv[ixj] = a;
                        int t = si[i]; si[i] = si[ixj]; si[ixj] = t;
                    }
                }
            }
            __syncthreads();
        }
    }
    float mx = sv[NN-1];
    if (tid == 0) g_s2max[bh] = mx;
    for (int i = tid; i < NN; i += 256) {
        float d = sv[i] - mx;
        float e = expf(d), f = expf(0.2f * d);
        fe[i] = e; ff[i] = f;
        g_s2s[bh*NN + i] = sv[i];
        g_E2s[bh*NN + i] = e;
        g_F2s[bh*NN + i] = f;
        g_perm[bh*NN + i] = si[i];
    }
    __syncthreads();
    if (tid == 0) {               // exclusive prefix of F2
        float acc = 0.f;
        for (int i = 0; i < NN; i++) { g_preF2[bh*(NN+1) + i] = acc; acc += ff[i]; }
        g_preF2[bh*(NN+1) + NN] = acc;
    }
    if (tid == 32) {              // inclusive-from suffix of E2
        float acc = 0.f;
        g_sufE2[bh*(NN+1) + NN] = 0.f;
        for (int i = NN-1; i >= 0; i--) { acc += fe[i]; g_sufE2[bh*(NN+1) + i] = acc; }
    }
}

// Per-chunk sums of F2*Wh and E2*Wh (sorted order). grid(NCH, BH), block HID.
__global__ void chunk_sum(const float* __restrict__ Wh) {
    int c = blockIdx.x, bh = blockIdx.y, o = threadIdx.x;
    int h = bh % NH, b = bh / NH;
    const float* whb = Wh + (size_t)b * NN * FDIM + h * HID + o;
    float aF = 0.f, aE = 0.f;
    for (int j = 0; j < CH; j++) {
        int i = c*CH + j;
        int m = g_perm[bh*NN + i];
        float w = whb[(size_t)m * FDIM];
        aF += g_F2s[bh*NN + i] * w;
        aE += g_E2s[bh*NN + i] * w;
    }
    g_chunkF[(bh*NCH + c)*HID + o] = aF;
    g_chunkE[(bh*NCH + c)*HID + o] = aE;
}

// Write full PreF (exclusive) / SufE (inclusive-from) tables. grid(NCH, BH), block HID.
__global__ void scan_write(const float* __restrict__ Wh) {
    __shared__ float wcache[CH*HID];
    int c = blockIdx.x, bh = blockIdx.y, o = threadIdx.x;
    int h = bh % NH, b = bh / NH;
    const float* whb = Wh + (size_t)b * NN * FDIM + h * HID + o;
    float offF = 0.f, offE = 0.f;
    for (int c2 = 0; c2 < c; c2++)       offF += g_chunkF[(bh*NCH + c2)*HID + o];
    for (int c2 = c+1; c2 < NCH; c2++)   offE += g_chunkE[(bh*NCH + c2)*HID + o];
    size_t base = ((size_t)bh*(NN+1))*HID + o;
    float accF = offF;
    for (int j = 0; j < CH; j++) {
        int i = c*CH + j;
        int m = g_perm[bh*NN + i];
        float w = whb[(size_t)m * FDIM];
        wcache[j*HID + o] = w;
        g_PreF[base + (size_t)i*HID] = accF;
        accF += g_F2s[bh*NN + i] * w;
    }
    if (c == NCH-1) {
        g_PreF[base + (size_t)NN*HID] = accF;
        g_SufE[base + (size_t)NN*HID] = 0.f;
    }
    float accE = offE;
    for (int j = CH-1; j >= 0; j--) {
        int i = c*CH + j;
        accE += g_E2s[bh*NN + i] * wcache[j*HID + o];
        g_SufE[base + (size_t)i*HID] = accE;
    }
}

// out[b,n,h*64+o] via binary search + 2-term combine. grid(NN/4, BH), block 256.
__global__ void apply_attn(const float* __restrict__ s1, float* __restrict__ out) {
    int bh = blockIdx.y, h = bh % NH, b = bh / NH;
    int n = blockIdx.x * 4 + (threadIdx.x >> 6);
    int o = threadIdx.x & 63;
    float s1v = s1[bh*NN + n];
    float mx = g_s2max[bh];
    float u = s1v + mx;
    float rmax = u > 0.f ? u : 0.2f * u;
    float E1 = expf(u - rmax);
    float F1 = expf(0.2f * u - rmax);
    float thr = -s1v;
    const float* ss = g_s2s + bh*NN;
    int lo = 0, hi = NN;
    while (lo < hi) {
        int mid = (lo + hi) >> 1;
        if (ss[mid] > thr) hi = mid; else lo = mid + 1;
    }
    int k = lo;
    size_t idx = ((size_t)bh*(NN+1) + k)*HID + o;
    float num = E1 * g_SufE[idx] + F1 * g_PreF[idx];
    float den = E1 * g_sufE2[bh*(NN+1) + k] + F1 * g_preF2[bh*(NN+1) + k];
    out[((size_t)(b*NN + n))*FDIM + h*HID + o] = num / den;
}

static void run_gat_layer(const float* hin, const float* B, const float* a,
                          float* Wh, float* hout, int K) {
    float *s1, *s2;
    cudaGetSymbolAddress((void**)&s1, g_s1);
    cudaGetSymbolAddress((void**)&s2, g_s2);
    sgemm<<<dim3(BN/64, FDIM/64), 256>>>(hin, B, nullptr, Wh, BN, FDIM, K);
    score_kernel<<<BHN/8, 256>>>(Wh, a, s1, s2);
    sort_prep<<<BH, 256>>>(s2);
    chunk_sum<<<dim3(NCH, BH), HID>>>(Wh);
    scan_write<<<dim3(NCH, BH), HID>>>(Wh);
    apply_attn<<<dim3(NN/4, BH), 256>>>(s1, hout);
}

extern "C" void kernel_launch(void* const* d_in, const int* in_sizes, int n_in,
                              void* d_out, int out_size) {
    const float* x    = (const float*)d_in[0];
    const float* ip_w = (const float*)d_in[1];
    const float* ip_b = (const float*)d_in[2];
    const float* w0   = (const float*)d_in[3];
    const float* a0   = (const float*)d_in[4];
    const float* w1   = (const float*)d_in[5];
    const float* a1   = (const float*)d_in[6];
    const float* pw   = (const float*)d_in[7];
    const float* pb   = (const float*)d_in[8];
    float* out = (float*)d_out;

    float *h0, *Wh, *hc1, *hc2, *B0, *B1;
    cudaGetSymbolAddress((void**)&h0,  g_h0);
    cudaGetSymbolAddress((void**)&Wh,  g_Wh);
    cudaGetSymbolAddress((void**)&hc1, g_hc1);
    cudaGetSymbolAddress((void**)&hc2, g_hc2);
    cudaGetSymbolAddress((void**)&B0,  g_B0);
    cudaGetSymbolAddress((void**)&B1,  g_B1);

    prep_B<<<512, 256>>>(w0, w1);

    // input projection: h0 = x @ ip_w + ip_b   [12288,16]x[16,64]
    sgemm<<<dim3(BN/64, HID/64), 256>>>(x, ip_w, ip_b, h0, BN, HID, INDIM);

    run_gat_layer(h0,  B0, a0, Wh, hc1, HID);   // GAT layer 0
    run_gat_layer(hc1, B1, a1, Wh, hc2, FDIM);  // GAT layer 1

    // output projection: out = hc2 @ proj_w + proj_b   [12288,512]x[512,128]
    sgemm<<<dim3(BN/64, EMB/64), 256>>>(hc2, pw, pb, out, BN, EMB, FDIM);
}

// round 4
// speedup vs baseline: 2.5813x; 1.4420x over previous
#include <cuda_runtime.h>
#include <math.h>
#include <stdint.h>

#define BSZ 16
#define NN 768
#define INDIM 16
#define HID 64
#define EMB 128
#define NH 8
#define BN (BSZ*NN)        // 12288
#define FDIM (NH*HID)      // 512
#define BH (BSZ*NH)        // 128
#define BHN (BH*NN)        // 98304
#define CH 96
#define NCH 8              // CH*NCH = 768

// ---- static scratch (no cudaMalloc allowed) ----
__device__ float g_h0 [BN*HID];
__device__ float g_Wh [BN*FDIM];
__device__ float g_hc1[BN*FDIM];
__device__ float g_hc2[BN*FDIM];
__device__ float g_s1[BHN], g_s2[BHN];
__device__ float g_s2s[BHN], g_E2s[BHN], g_F2s[BHN];
__device__ int   g_perm[BHN];
__device__ float g_s2max[BH];
__device__ float g_preF2[BH*(NN+1)], g_sufE2[BH*(NN+1)];
__device__ float g_PreF[(size_t)BH*(NN+1)*HID];
__device__ float g_SufE[(size_t)BH*(NN+1)*HID];
__device__ float g_chunkF[BH*NCH*HID], g_chunkE[BH*NCH*HID];
__device__ float g_B0t[FDIM*HID];     // [512, 64]  K-major (N,K)
__device__ float g_B1t[FDIM*FDIM];    // [512, 512]
__device__ float g_pwT[EMB*FDIM];     // [128, 512]

// ===================== HMMA tf32 GEMM =====================
__device__ __forceinline__ uint32_t smem_u32(const void* p) {
    uint32_t a;
    asm("{ .reg .u64 t; cvta.to.shared.u64 t, %1; cvt.u32.u64 %0, t; }" : "=r"(a) : "l"(p));
    return a;
}
__device__ __forceinline__ uint32_t f2tf(float x) {
    uint32_t u; asm("cvt.rna.tf32.f32 %0, %1;" : "=r"(u) : "f"(x)); return u;
}
__device__ __forceinline__ void mma_tf32(float* d, const uint32_t* a, const uint32_t* b) {
    asm volatile("mma.sync.aligned.m16n8k8.row.col.f32.tf32.tf32.f32 "
                 "{%0,%1,%2,%3}, {%4,%5,%6,%7}, {%8,%9}, {%0,%1,%2,%3};"
                 : "+f"(d[0]), "+f"(d[1]), "+f"(d[2]), "+f"(d[3])
                 : "r"(a[0]), "r"(a[1]), "r"(a[2]), "r"(a[3]), "r"(b[0]), "r"(b[1]));
}
#define CP16(dst, src) \
    asm volatile("cp.async.ca.shared.global [%0], [%1], 16;" :: "r"(dst), "l"(src) : "memory")
#define CP_COMMIT()  asm volatile("cp.async.commit_group;" ::: "memory")
#define CP_WAIT0()   asm volatile("cp.async.wait_group 0;" ::: "memory")

// tile rows are 32 floats (128B); 16B-chunk XOR swizzle -> conflict-free frag LDS
__device__ __forceinline__ int swz(int row, int k) {
    return row * 32 + ((((k >> 2) ^ (row & 7)) << 2) | (k & 3));
}

// C[M,Ncols] = A[M,K] @ Bt[Ncols,K]^T (+bias). CTA tile 128x64, 4 warps (64x32 each), BK=32.
__global__ __launch_bounds__(128)
void tf32_gemm(const float* __restrict__ A, const float* __restrict__ Bt,
               const float* __restrict__ bias, float* __restrict__ C,
               int N, int K) {
    __shared__ float As[2][128 * 32];   // 16KB x2
    __shared__ float Bs[2][64 * 32];    //  8KB x2   -> 48KB total
    const int tid = threadIdx.x;
    const int wid = tid >> 5, lane = tid & 31;
    const int r = lane >> 2, c = lane & 3;
    const int warp_m = (wid & 1) * 64, warp_n = (wid >> 1) * 32;
    const int m0 = blockIdx.x * 128, n0 = blockIdx.y * 64;

    uint32_t asb[2] = { smem_u32(&As[0][0]), smem_u32(&As[1][0]) };
    uint32_t bsb[2] = { smem_u32(&Bs[0][0]), smem_u32(&Bs[1][0]) };

    float acc[4][4][4] = {};
    const int NC = K >> 5;

    // stage chunk 0
    {
#pragma unroll
        for (int j = 0; j < 8; j++) {
            int u = tid + j * 128, row = u >> 3, ch = u & 7;
            CP16(asb[0] + (uint32_t)(row * 32 + ((ch ^ (row & 7)) << 2)) * 4,
                 A + (size_t)(m0 + row) * K + ch * 4);
        }
#pragma unroll
        for (int j = 0; j < 4; j++) {
            int u = tid + j * 128, row = u >> 3, ch = u & 7;
            CP16(bsb[0] + (uint32_t)(row * 32 + ((ch ^ (row & 7)) << 2)) * 4,
                 Bt + (size_t)(n0 + row) * K + ch * 4);
        }
        CP_COMMIT();
    }

    for (int i = 0; i < NC; i++) {
        CP_WAIT0();
        __syncthreads();
        if (i + 1 < NC) {
            int nb = (i + 1) & 1, kc = (i + 1) * 32;
#pragma unroll
            for (int j = 0; j < 8; j++) {
                int u = tid + j * 128, row = u >> 3, ch = u & 7;
                CP16(asb[nb] + (uint32_t)(row * 32 + ((ch ^ (row & 7)) << 2)) * 4,
                     A + (size_t)(m0 + row) * K + kc + ch * 4);
            }
#pragma unroll
            for (int j = 0; j < 4; j++) {
                int u = tid + j * 128, row = u >> 3, ch = u & 7;
                CP16(bsb[nb] + (uint32_t)(row * 32 + ((ch ^ (row & 7)) << 2)) * 4,
                     Bt + (size_t)(n0 + row) * K + kc + ch * 4);
            }
            CP_COMMIT();
        }
        const float* as = As[i & 1];
        const float* bs = Bs[i & 1];
#pragma unroll
        for (int ks = 0; ks < 4; ks++) {
            uint32_t af[4][4], bf[4][2];
#pragma unroll
            for (int mt = 0; mt < 4; mt++) {
                int rb = warp_m + mt * 16 + r;
                af[mt][0] = f2tf(as[swz(rb,     ks * 8 + c)]);
                af[mt][1] = f2tf(as[swz(rb + 8, ks * 8 + c)]);
                af[mt][2] = f2tf(as[swz(rb,     ks * 8 + c + 4)]);
                af[mt][3] = f2tf(as[swz(rb + 8, ks * 8 + c + 4)]);
            }
#pragma unroll
            for (int nt = 0; nt < 4; nt++) {
                int nb = warp_n + nt * 8 + r;
                bf[nt][0] = f2tf(bs[swz(nb, ks * 8 + c)]);
                bf[nt][1] = f2tf(bs[swz(nb, ks * 8 + c + 4)]);
            }
#pragma unroll
            for (int mt = 0; mt < 4; mt++)
#pragma unroll
                for (int nt = 0; nt < 4; nt++)
                    mma_tf32(acc[mt][nt], af[mt], bf[nt]);
        }
        __syncthreads();
    }

    // epilogue: C frag c0/c1 = (row, 2c/2c+1), c2/c3 = (row+8, ...)
#pragma unroll
    for (int mt = 0; mt < 4; mt++) {
#pragma unroll
        for (int nt = 0; nt < 4; nt++) {
            int row = m0 + warp_m + mt * 16 + r;
            int col = n0 + warp_n + nt * 8 + c * 2;
            float bx = 0.f, by = 0.f;
            if (bias) { bx = bias[col]; by = bias[col + 1]; }
            float2 v0 = { acc[mt][nt][0] + bx, acc[mt][nt][1] + by };
            float2 v1 = { acc[mt][nt][2] + bx, acc[mt][nt][3] + by };
            *(float2*)&C[(size_t)row * N + col] = v0;
            *(float2*)&C[(size_t)(row + 8) * N + col] = v1;
        }
    }
}

// ===================== non-GEMM kernels =====================

__global__ void prep_B(const float* __restrict__ w0, const float* __restrict__ w1,
                       const float* __restrict__ pw) {
    int i0 = blockIdx.x * blockDim.x + threadIdx.x;
    int stride = gridDim.x * blockDim.x;
    for (int i = i0; i < FDIM*HID; i += stride) {
        int n = i / HID, f = i % HID;
        g_B0t[i] = w0[(n / HID) * (HID*HID) + f * HID + (n % HID)];
    }
    for (int i = i0; i < FDIM*FDIM; i += stride) {
        int n = i / FDIM, f = i % FDIM;
        g_B1t[i] = w1[(n / HID) * (FDIM*HID) + f * HID + (n % HID)];
    }
    for (int i = i0; i < EMB*FDIM; i += stride) {
        int n = i / FDIM, k = i % FDIM;
        g_pwT[i] = pw[k * EMB + n];
    }
}

// small fp32 SGEMM for the input projection only (K=16)
__global__ void sgemm(const float* __restrict__ A, const float* __restrict__ B,
                      const float* __restrict__ bias, float* __restrict__ C,
                      int M, int N, int K) {
    __shared__ float As[16][64];
    __shared__ float Bs[16][64];
    int tid = threadIdx.x;
    int m0 = blockIdx.x * 64, n0 = blockIdx.y * 64;
    int tx = tid & 15, ty = tid >> 4;
    int arow = tid >> 2, acol = (tid & 3) * 4;
    int brow = tid >> 4, bcol = (tid & 15) * 4;
    float acc[4][4] = {};
    for (int kc = 0; kc < K; kc += 16) {
        float4 av = *(const float4*)&A[(size_t)(m0 + arow) * K + kc + acol];
        As[acol+0][arow] = av.x; As[acol+1][arow] = av.y;
        As[acol+2][arow] = av.z; As[acol+3][arow] = av.w;
        *(float4*)&Bs[brow][bcol] = *(const float4*)&B[(size_t)(kc + brow) * N + n0 + bcol];
        __syncthreads();
#pragma unroll
        for (int k = 0; k < 16; k++) {
            float4 a4 = *(float4*)&As[k][ty*4];
            float4 b4 = *(float4*)&Bs[k][tx*4];
            float a[4] = {a4.x, a4.y, a4.z, a4.w};
            float b[4] = {b4.x, b4.y, b4.z, b4.w};
#pragma unroll
            for (int i = 0; i < 4; i++)
#pragma unroll
                for (int j = 0; j < 4; j++) acc[i][j] += a[i] * b[j];
        }
        __syncthreads();
    }
#pragma unroll
    for (int i = 0; i < 4; i++) {
        int m = m0 + ty*4 + i, n = n0 + tx*4;
        float4 v = {acc[i][0], acc[i][1], acc[i][2], acc[i][3]};
        if (bias) { v.x += bias[n]; v.y += bias[n+1]; v.z += bias[n+2]; v.w += bias[n+3]; }
        *(float4*)&C[(size_t)m * N + n] = v;
    }
}

__global__ void score_kernel(const float* __restrict__ Wh, const float* __restrict__ a,
                             float* __restrict__ s1, float* __restrict__ s2) {
    int warp = (blockIdx.x * blockDim.x + threadIdx.x) >> 5;
    int lane = threadIdx.x & 31;
    if (warp >= BHN) return;
    int n = warp % NN, bh = warp / NN, h = bh % NH, b = bh / NH;
    const float* wr = Wh + (size_t)(b*NN + n) * FDIM + h * HID;
    const float* ah = a + h * 2 * HID;
    float v0 = wr[lane], v1 = wr[lane + 32];
    float p1 = v0 * ah[lane]       + v1 * ah[lane + 32];
    float p2 = v0 * ah[HID + lane] + v1 * ah[HID + lane + 32];
#pragma unroll
    for (int off = 16; off; off >>= 1) {
        p1 += __shfl_xor_sync(0xffffffffu, p1, off);
        p2 += __shfl_xor_sync(0xffffffffu, p2, off);
    }
    if (lane == 0) { s1[warp] = p1; s2[warp] = p2; }
}

__global__ void sort_prep(const float* __restrict__ s2) {
    __shared__ float sv[1024];
    __shared__ int   si[1024];
    __shared__ float fe[NN], ff[NN];
    int bh = blockIdx.x, tid = threadIdx.x;
    for (int i = tid; i < 1024; i += 256) {
        sv[i] = (i < NN) ? s2[bh*NN + i] : 3.0e38f;
        si[i] = i;
    }
    __syncthreads();
    for (int k = 2; k <= 1024; k <<= 1) {
        for (int j = k >> 1; j > 0; j >>= 1) {
            for (int i = tid; i < 1024; i += 256) {
                int ixj = i ^ j;
                if (ixj > i) {
                    bool up = ((i & k) == 0);
                    float a = sv[i], b = sv[ixj];
                    if ((a > b) == up) {
                        sv[i] = b; sv[ixj] = a;
                        int t = si[i]; si[i] = si[ixj]; si[ixj] = t;
                    }
                }
            }
            __syncthreads();
        }
    }
    float mx = sv[NN-1];
    if (tid == 0) g_s2max[bh] = mx;
    for (int i = tid; i < NN; i += 256) {
        float d = sv[i] - mx;
        float e = expf(d), f = expf(0.2f * d);
        fe[i] = e; ff[i] = f;
        g_s2s[bh*NN + i] = sv[i];
        g_E2s[bh*NN + i] = e;
        g_F2s[bh*NN + i] = f;
        g_perm[bh*NN + i] = si[i];
    }
    __syncthreads();
    if (tid == 0) {
        float acc = 0.f;
        for (int i = 0; i < NN; i++) { g_preF2[bh*(NN+1) + i] = acc; acc += ff[i]; }
        g_preF2[bh*(NN+1) + NN] = acc;
    }
    if (tid == 32) {
        float acc = 0.f;
        g_sufE2[bh*(NN+1) + NN] = 0.f;
        for (int i = NN-1; i >= 0; i--) { acc += fe[i]; g_sufE2[bh*(NN+1) + i] = acc; }
    }
}

__global__ void chunk_sum(const float* __restrict__ Wh) {
    int c = blockIdx.x, bh = blockIdx.y, o = threadIdx.x;
    int h = bh % NH, b = bh / NH;
    const float* whb = Wh + (size_t)b * NN * FDIM + h * HID + o;
    float aF = 0.f, aE = 0.f;
    for (int j = 0; j < CH; j++) {
        int i = c*CH + j;
        int m = g_perm[bh*NN + i];
        float w = whb[(size_t)m * FDIM];
        aF += g_F2s[bh*NN + i] * w;
        aE += g_E2s[bh*NN + i] * w;
    }
    g_chunkF[(bh*NCH + c)*HID + o] = aF;
    g_chunkE[(bh*NCH + c)*HID + o] = aE;
}

__global__ void scan_write(const float* __restrict__ Wh) {
    __shared__ float wcache[CH*HID];
    int c = blockIdx.x, bh = blockIdx.y, o = threadIdx.x;
    int h = bh % NH, b = bh / NH;
    const float* whb = Wh + (size_t)b * NN * FDIM + h * HID + o;
    float offF = 0.f, offE = 0.f;
    for (int c2 = 0; c2 < c; c2++)       offF += g_chunkF[(bh*NCH + c2)*HID + o];
    for (int c2 = c+1; c2 < NCH; c2++)   offE += g_chunkE[(bh*NCH + c2)*HID + o];
    size_t base = ((size_t)bh*(NN+1))*HID + o;
    float accF = offF;
    for (int j = 0; j < CH; j++) {
        int i = c*CH + j;
        int m = g_perm[bh*NN + i];
        float w = whb[(size_t)m * FDIM];
        wcache[j*HID + o] = w;
        g_PreF[base + (size_t)i*HID] = accF;
        accF += g_F2s[bh*NN + i] * w;
    }
    if (c == NCH-1) {
        g_PreF[base + (size_t)NN*HID] = accF;
        g_SufE[base + (size_t)NN*HID] = 0.f;
    }
    float accE = offE;
    for (int j = CH-1; j >= 0; j--) {
        int i = c*CH + j;
        accE += g_E2s[bh*NN + i] * wcache[j*HID + o];
        g_SufE[base + (size_t)i*HID] = accE;
    }
}

__global__ void apply_attn(const float* __restrict__ s1, float* __restrict__ out) {
    int bh = blockIdx.y, h = bh % NH, b = bh / NH;
    int n = blockIdx.x * 4 + (threadIdx.x >> 6);
    int o = threadIdx.x & 63;
    float s1v = s1[bh*NN + n];
    float mx = g_s2max[bh];
    float u = s1v + mx;
    float rmax = u > 0.f ? u : 0.2f * u;
    float E1 = expf(u - rmax);
    float F1 = expf(0.2f * u - rmax);
    float thr = -s1v;
    const float* ss = g_s2s + bh*NN;
    int lo = 0, hi = NN;
    while (lo < hi) {
        int mid = (lo + hi) >> 1;
        if (ss[mid] > thr) hi = mid; else lo = mid + 1;
    }
    int k = lo;
    size_t idx = ((size_t)bh*(NN+1) + k)*HID + o;
    float num = E1 * g_SufE[idx] + F1 * g_PreF[idx];
    float den = E1 * g_sufE2[bh*(NN+1) + k] + F1 * g_preF2[bh*(NN+1) + k];
    out[((size_t)(b*NN + n))*FDIM + h*HID + o] = num / den;
}

static void run_gat_layer(const float* hin, const float* Bt, const float* a,
                          float* Wh, float* hout, int K) {
    float *s1, *s2;
    cudaGetSymbolAddress((void**)&s1, g_s1);
    cudaGetSymbolAddress((void**)&s2, g_s2);
    tf32_gemm<<<dim3(BN/128, FDIM/64), 128>>>(hin, Bt, nullptr, Wh, FDIM, K);
    score_kernel<<<BHN/8, 256>>>(Wh, a, s1, s2);
    sort_prep<<<BH, 256>>>(s2);
    chunk_sum<<<dim3(NCH, BH), HID>>>(Wh);
    scan_write<<<dim3(NCH, BH), HID>>>(Wh);
    apply_attn<<<dim3(NN/4, BH), 256>>>(s1, hout);
}

extern "C" void kernel_launch(void* const* d_in, const int* in_sizes, int n_in,
                              void* d_out, int out_size) {
    const float* x    = (const float*)d_in[0];
    const float* ip_w = (const float*)d_in[1];
    const float* ip_b = (const float*)d_in[2];
    const float* w0   = (const float*)d_in[3];
    const float* a0   = (const float*)d_in[4];
    const float* w1   = (const float*)d_in[5];
    const float* a1   = (const float*)d_in[6];
    const float* pw   = (const float*)d_in[7];
    const float* pb   = (const float*)d_in[8];
    float* out = (float*)d_out;

    float *h0, *Wh, *hc1, *hc2, *B0t, *B1t, *pwT;
    cudaGetSymbolAddress((void**)&h0,  g_h0);
    cudaGetSymbolAddress((void**)&Wh,  g_Wh);
    cudaGetSymbolAddress((void**)&hc1, g_hc1);
    cudaGetSymbolAddress((void**)&hc2, g_hc2);
    cudaGetSymbolAddress((void**)&B0t, g_B0t);
    cudaGetSymbolAddress((void**)&B1t, g_B1t);
    cudaGetSymbolAddress((void**)&pwT, g_pwT);

    prep_B<<<512, 256>>>(w0, w1, pw);

    // input projection: h0 = x @ ip_w + ip_b   [12288,16]x[16,64] (tiny, fp32)
    sgemm<<<dim3(BN/64, HID/64), 256>>>(x, ip_w, ip_b, h0, BN, HID, INDIM);

    run_gat_layer(h0,  B0t, a0, Wh, hc1, HID);   // GAT layer 0
    run_gat_layer(hc1, B1t, a1, Wh, hc2, FDIM);  // GAT layer 1

    // output projection: out = hc2 @ proj_w + proj_b   [12288,512]x[512,128]
    tf32_gemm<<<dim3(BN/128, EMB/64), 128>>>(hc2, pwT, pb, out, EMB, FDIM);
}